// round 10
// baseline (speedup 1.0000x reference)
#include <cuda_runtime.h>
#include <cuda_bf16.h>
#include <cstdint>

typedef unsigned int u32;
typedef unsigned short u16;

// ---------------------------------------------------------------------------
// Device-global scratch (no allocations allowed). All bf16 stored as ushort.
// ---------------------------------------------------------------------------
__device__ __align__(16) u16 g_XTh[8u*256*2048], g_XTl[8u*256*2048];  // X^T per (b,q): [f=256][t=2048]
__device__ __align__(16) u16 g_Xnh[2u*2048*1024], g_Xnl[2u*2048*1024];// hidden split: [b][t][e]
__device__ __align__(16) u16 g_CTh[16u*65536],   g_CTl[16u*65536];    // C^T per (a,q): [g=256][f=256]
__device__ __align__(16) u16 g_qh [4u*262144],   g_ql [4u*262144];    // queries split: [a][e=256][k=1024]
__device__ __align__(16) float g_Gp[8u*8*65536];                      // gram fp32 partials (z8)
__device__ __align__(16) u16 g_Gh[8u*65536], g_Gl[8u*65536];          // G per (b,q): [256][256] (symmetric)
__device__ __align__(16) float g_Tf[8u*262144];                       // T^T fp32: [ba][g=256][k=1024]
__device__ __align__(16) u16 g_TTh[8u*262144], g_TTl[8u*262144];      // T^T split
__device__ __align__(16) float g_Mp[4u*8*65536];                      // fold fp32 partials (z4)
__device__ __align__(16) u16 g_Mth[8u*65536], g_Mtl[8u*65536];        // M^T per (b,a): [g=256][e=256]

// ---------------------------------------------------------------------------
__device__ __forceinline__ void mma_bf16(float* c, const u32* a, const u32* b) {
    asm("mma.sync.aligned.m16n8k16.row.col.f32.bf16.bf16.f32 "
        "{%0,%1,%2,%3}, {%4,%5,%6,%7}, {%8,%9}, {%0,%1,%2,%3};"
        : "+f"(c[0]), "+f"(c[1]), "+f"(c[2]), "+f"(c[3])
        : "r"(a[0]), "r"(a[1]), "r"(a[2]), "r"(a[3]), "r"(b[0]), "r"(b[1]));
}
__device__ __forceinline__ void ldsm_x4(u32* r, u32 saddr) {
    asm volatile("ldmatrix.sync.aligned.m8n8.x4.shared.b16 {%0,%1,%2,%3}, [%4];"
                 : "=r"(r[0]), "=r"(r[1]), "=r"(r[2]), "=r"(r[3]) : "r"(saddr));
}
__device__ __forceinline__ void cpa16(u32 dst, const void* src) {
    asm volatile("cp.async.cg.shared.global [%0], [%1], 16;" :: "r"(dst), "l"(src));
}
__device__ __forceinline__ void cpa_commit() {
    asm volatile("cp.async.commit_group;" ::: "memory");
}

__device__ __forceinline__ void split2(float v, u16& h, u16& l) {
    __nv_bfloat16 bh = __float2bfloat16(v);
    __nv_bfloat16 bl = __float2bfloat16(v - __bfloat162float(bh));
    h = *reinterpret_cast<u16*>(&bh);
    l = *reinterpret_cast<u16*>(&bl);
}

// SMEM tile: 128 rows x 32 bf16, row stride 40 u16 (80B: 16B-aligned fills,
// conflict-free for ldmatrix row fetches).
constexpr int SK = 40;
constexpr int TSZ = 128 * SK;                   // u16 per tile
constexpr int BUF = 4 * TSZ;                    // u16 per buffer (Ah,Al,Bh,Bl)
constexpr int SMEM_GEMM = 2 * BUF * 2;          // bytes = 81920

// ---------------------------------------------------------------------------
// cp.async fill of one 4-tile chunk (A/B hi+lo, 128x32 each). 128 threads.
// ---------------------------------------------------------------------------
__device__ __forceinline__ void issue_chunk(u16* buf,
    const u16* __restrict__ Ah, const u16* __restrict__ Al, size_t lda,
    const u16* __restrict__ Bh, const u16* __restrict__ Bl, size_t ldb, int k0)
{
    u16* sAh = buf;           u16* sAl = buf + TSZ;
    u16* sBh = buf + 2 * TSZ; u16* sBl = buf + 3 * TSZ;
    #pragma unroll
    for (int u = threadIdx.x; u < 512; u += 128) {
        int row = u >> 2, c = u & 3;
        int so = row * SK + c * 8;
        size_t goA = (size_t)row * lda + k0 + c * 8;
        size_t goB = (size_t)row * ldb + k0 + c * 8;
        cpa16((u32)__cvta_generic_to_shared(sAh + so), Ah + goA);
        cpa16((u32)__cvta_generic_to_shared(sAl + so), Al + goA);
        cpa16((u32)__cvta_generic_to_shared(sBh + so), Bh + goB);
        cpa16((u32)__cvta_generic_to_shared(sBl + so), Bl + goB);
    }
    cpa_commit();
}

// ---------------------------------------------------------------------------
// Core: C[128,128](fp32) = sum_k (Ah+Al)[128,k]*(Bh+Bl)[128,k]^T (hh+hl+lh)
// 128 threads = 4 warps (2m x 2n), warp tile 64x64. Double-buffered cp.async,
// ldmatrix.x4 fragment loads (B loads two n8 tiles per instruction).
// ---------------------------------------------------------------------------
__device__ void gemm_ss(const u16* __restrict__ Ah, const u16* __restrict__ Al, size_t lda,
                        const u16* __restrict__ Bh, const u16* __restrict__ Bl, size_t ldb,
                        int kbeg, int kend, float* __restrict__ C, size_t ldc)
{
    extern __shared__ __align__(16) u16 dsmem[];
    u16* bufs[2] = { dsmem, dsmem + BUF };

    const int tid = threadIdx.x, w = tid >> 5, lane = tid & 31;
    const int wm = (w >> 1) * 64, wn = (w & 1) * 64;
    const int ty = lane >> 2, tk = lane & 3;

    float acc[4][8][4] = {};   // [mt][nt][frag]  (64x64 warp tile)

    const int nchunk = (kend - kbeg) >> 5;
    issue_chunk(bufs[0], Ah, Al, lda, Bh, Bl, ldb, kbeg);

    for (int i = 0; i < nchunk; i++) {
        const bool has_next = (i + 1) < nchunk;
        if (has_next)
            issue_chunk(bufs[(i + 1) & 1], Ah, Al, lda, Bh, Bl, ldb, kbeg + (i + 1) * 32);
        if (has_next) asm volatile("cp.async.wait_group 1;" ::: "memory");
        else          asm volatile("cp.async.wait_group 0;" ::: "memory");
        __syncthreads();

        u16* buf = bufs[i & 1];
        const u32 bAh = (u32)__cvta_generic_to_shared(buf);
        const u32 bAl = bAh + TSZ * 2;
        const u32 bBh = bAh + 2 * TSZ * 2;
        const u32 bBl = bAh + 3 * TSZ * 2;

        #pragma unroll
        for (int ks = 0; ks < 2; ks++) {
            const int kb = ks * 16;
            // A fragments for all 4 mt (hi+lo): 8 ldmatrix.x4
            u32 ah[4][4], al[4][4];
            #pragma unroll
            for (int mt = 0; mt < 4; mt++) {
                u32 off = ((wm + mt * 16 + (lane & 15)) * SK + kb + (lane >> 4) * 8) * 2;
                ldsm_x4(ah[mt], bAh + off);
                ldsm_x4(al[mt], bAl + off);
            }
            // B in pairs of n8 tiles: 4 np x (hi+lo) ldmatrix.x4
            #pragma unroll
            for (int np = 0; np < 4; np++) {
                u32 off = ((wn + np * 16 + (lane & 7) + ((lane >> 4) & 1) * 8) * SK
                           + kb + ((lane >> 3) & 1) * 8) * 2;
                u32 bh4[4], bl4[4];
                ldsm_x4(bh4, bBh + off);
                ldsm_x4(bl4, bBl + off);
                #pragma unroll
                for (int mt = 0; mt < 4; mt++) {
                    mma_bf16(acc[mt][2*np],   ah[mt], bh4);
                    mma_bf16(acc[mt][2*np],   ah[mt], bl4);
                    mma_bf16(acc[mt][2*np],   al[mt], bh4);
                    mma_bf16(acc[mt][2*np+1], ah[mt], bh4 + 2);
                    mma_bf16(acc[mt][2*np+1], ah[mt], bl4 + 2);
                    mma_bf16(acc[mt][2*np+1], al[mt], bh4 + 2);
                }
            }
        }
        __syncthreads();
    }

    // epilogue (fp32)
    #pragma unroll
    for (int mt = 0; mt < 4; mt++) {
        int m = wm + mt * 16 + ty;
        #pragma unroll
        for (int nt = 0; nt < 8; nt++) {
            int n = wn + nt * 8 + tk * 2;
            *reinterpret_cast<float2*>(&C[(size_t)m * ldc + n]) =
                make_float2(acc[mt][nt][0], acc[mt][nt][1]);
            *reinterpret_cast<float2*>(&C[(size_t)(m + 8) * ldc + n]) =
                make_float2(acc[mt][nt][2], acc[mt][nt][3]);
        }
    }
}

// ---------------------------------------------------------------------------
// Prep kernels (fp32 -> bf16 hi/lo, with transposes)
// ---------------------------------------------------------------------------
__global__ void __launch_bounds__(256) p_hid(const float* __restrict__ hidden)
{
    __shared__ float tile[64][65];
    const int tid = threadIdx.x;
    const int e0 = blockIdx.x * 64, t0 = blockIdx.y * 64, b = blockIdx.z;
    const size_t base = (size_t)b * 2048 * 1024;
    for (int i = tid; i < 4096; i += 256) {
        int r = i >> 6, c = i & 63;
        float v = hidden[base + (size_t)(t0 + r) * 1024 + e0 + c];
        tile[r][c] = v;
        u16 h, l; split2(v, h, l);
        size_t o = base + (size_t)(t0 + r) * 1024 + e0 + c;
        g_Xnh[o] = h; g_Xnl[o] = l;
    }
    __syncthreads();
    const int pair = b * 4 + (e0 >> 8), f0 = e0 & 255;
    for (int i = tid; i < 4096; i += 256) {
        int fl = i >> 6, tl = i & 63;
        u16 h, l; split2(tile[tl][fl], h, l);
        size_t o = (size_t)pair * 524288 + (size_t)(f0 + fl) * 2048 + t0 + tl;
        g_XTh[o] = h; g_XTl[o] = l;
    }
}

__global__ void __launch_bounds__(256) p_comb(const float* __restrict__ comb)
{
    __shared__ float tile[64][65];
    const int tid = threadIdx.x;
    const int g0 = blockIdx.x * 64, k0 = blockIdx.y * 64, a = blockIdx.z;
    for (int i = tid; i < 4096; i += 256) {
        int r = i >> 6, c = i & 63;
        tile[r][c] = comb[(size_t)a * 262144 + (size_t)(k0 + r) * 256 + g0 + c];
    }
    __syncthreads();
    const int q = k0 >> 8, f0 = k0 & 255;
    for (int i = tid; i < 4096; i += 256) {
        int gl = i >> 6, fl = i & 63;
        u16 h, l; split2(tile[fl][gl], h, l);
        size_t o = (size_t)(a * 4 + q) * 65536 + (size_t)(g0 + gl) * 256 + f0 + fl;
        g_CTh[o] = h; g_CTl[o] = l;
    }
}

__global__ void __launch_bounds__(256) p_q(const float* __restrict__ queries)
{
    const int i = blockIdx.x * 256 + threadIdx.x;      // 262144 float4
    float4 v = reinterpret_cast<const float4*>(queries)[i];
    ushort4 h, l;
    split2(v.x, h.x, l.x); split2(v.y, h.y, l.y);
    split2(v.z, h.z, l.z); split2(v.w, h.w, l.w);
    reinterpret_cast<ushort4*>(g_qh)[i] = h;
    reinterpret_cast<ushort4*>(g_ql)[i] = l;
}

// ---------------------------------------------------------------------------
// GEMM stages (128 threads each)
// ---------------------------------------------------------------------------
// Gram: D[f,f'] = sum_t XT[f,t] XT[f',t]  — grid (4, 8 pairs, 8 z)
__global__ void __launch_bounds__(128) k_gram()
{
    const int pair = blockIdx.y, z = blockIdx.z;
    const int m0 = (blockIdx.x >> 1) * 128, n0 = (blockIdx.x & 1) * 128;
    const u16* base_h = g_XTh + (size_t)pair * 524288;
    const u16* base_l = g_XTl + (size_t)pair * 524288;
    float* C = g_Gp + (size_t)(z * 8 + pair) * 65536 + (size_t)m0 * 256 + n0;
    gemm_ss(base_h + (size_t)m0 * 2048, base_l + (size_t)m0 * 2048, 2048,
            base_h + (size_t)n0 * 2048, base_l + (size_t)n0 * 2048, 2048,
            z * 256, z * 256 + 256, C, 256);
}

__global__ void __launch_bounds__(256) k_gred()
{
    const int i = blockIdx.x * 256 + threadIdx.x;      // 131072 float4
    const float4* P = reinterpret_cast<const float4*>(g_Gp);
    float4 s = P[i];
    #pragma unroll
    for (int z = 1; z < 8; z++) {
        float4 t = P[i + (size_t)z * 131072];
        s.x += t.x; s.y += t.y; s.z += t.z; s.w += t.w;
    }
    ushort4 h, l;
    split2(s.x, h.x, l.x); split2(s.y, h.y, l.y);
    split2(s.z, h.z, l.z); split2(s.w, h.w, l.w);
    reinterpret_cast<ushort4*>(g_Gh)[i] = h;
    reinterpret_cast<ushort4*>(g_Gl)[i] = l;
}

// B1: Tf[ba][g, q*256+f] = sum_{f'} CT[a,q][g,f'] G[b,q][f,f'] — grid (4, 32)
__global__ void __launch_bounds__(128) k_b1()
{
    const int combo = blockIdx.y, q = combo & 3, ba = combo >> 2;
    const int a = ba & 3, b = ba >> 2;
    const int m0 = (blockIdx.x >> 1) * 128, n0 = (blockIdx.x & 1) * 128;
    const u16* Ah = g_CTh + (size_t)(a * 4 + q) * 65536 + (size_t)m0 * 256;
    const u16* Al = g_CTl + (size_t)(a * 4 + q) * 65536 + (size_t)m0 * 256;
    const u16* Bh = g_Gh + (size_t)(b * 4 + q) * 65536 + (size_t)n0 * 256;
    const u16* Bl = g_Gl + (size_t)(b * 4 + q) * 65536 + (size_t)n0 * 256;
    float* C = g_Tf + (size_t)ba * 262144 + (size_t)m0 * 1024 + q * 256 + n0;
    gemm_ss(Ah, Al, 256, Bh, Bl, 256, 0, 256, C, 1024);
}

__global__ void __launch_bounds__(256) k_tred()
{
    const int i = blockIdx.x * 256 + threadIdx.x;      // 524288 float4
    float4 s = reinterpret_cast<const float4*>(g_Tf)[i];
    ushort4 h, l;
    split2(s.x, h.x, l.x); split2(s.y, h.y, l.y);
    split2(s.z, h.z, l.z); split2(s.w, h.w, l.w);
    reinterpret_cast<ushort4*>(g_TTh)[i] = h;
    reinterpret_cast<ushort4*>(g_TTl)[i] = l;
}

// B2: Mt[g,e] = sum_k TT[ba][g,k] q[a][e,k] — grid (4, 8 ba, 4 z)
__global__ void __launch_bounds__(128) k_b2()
{
    const int ba = blockIdx.y, z = blockIdx.z, a = ba & 3;
    const int m0 = (blockIdx.x >> 1) * 128, n0 = (blockIdx.x & 1) * 128;
    const u16* Ah = g_TTh + (size_t)ba * 262144 + (size_t)m0 * 1024;
    const u16* Al = g_TTl + (size_t)ba * 262144 + (size_t)m0 * 1024;
    const u16* Bh = g_qh + (size_t)a * 262144 + (size_t)n0 * 1024;
    const u16* Bl = g_ql + (size_t)a * 262144 + (size_t)n0 * 1024;
    float* C = g_Mp + (size_t)(z * 8 + ba) * 65536 + (size_t)m0 * 256 + n0;
    gemm_ss(Ah, Al, 1024, Bh, Bl, 1024, z * 256, z * 256 + 256, C, 256);
}

__global__ void __launch_bounds__(256) k_mred()
{
    const int i = blockIdx.x * 256 + threadIdx.x;      // 131072 float4
    const float4* P = reinterpret_cast<const float4*>(g_Mp);
    float4 s = P[i];
    #pragma unroll
    for (int z = 1; z < 4; z++) {
        float4 t = P[i + (size_t)z * 131072];
        s.x += t.x; s.y += t.y; s.z += t.z; s.w += t.w;
    }
    ushort4 h, l;
    split2(s.x, h.x, l.x); split2(s.y, h.y, l.y);
    split2(s.z, h.z, l.z); split2(s.w, h.w, l.w);
    reinterpret_cast<ushort4*>(g_Mth)[i] = h;
    reinterpret_cast<ushort4*>(g_Mtl)[i] = l;
}

// C: out[b,t,a*256+g] = sum_e Xn[b,t,a*256+e] Mt[ba][g,e] — grid (32, 8 ba)
__global__ void __launch_bounds__(128) k_c(float* __restrict__ out)
{
    const int ba = blockIdx.y, b = ba >> 2, a = ba & 3;
    const int m0 = (blockIdx.x >> 1) * 128, n0 = (blockIdx.x & 1) * 128;
    const u16* Ah = g_Xnh + (size_t)b * 2097152 + (size_t)m0 * 1024 + a * 256;
    const u16* Al = g_Xnl + (size_t)b * 2097152 + (size_t)m0 * 1024 + a * 256;
    const u16* Bh = g_Mth + (size_t)ba * 65536 + (size_t)n0 * 256;
    const u16* Bl = g_Mtl + (size_t)ba * 65536 + (size_t)n0 * 256;
    float* C = out + (size_t)b * 2097152 + (size_t)m0 * 1024 + a * 256 + n0;
    gemm_ss(Ah, Al, 1024, Bh, Bl, 256, 0, 256, C, 1024);
}

// ---------------------------------------------------------------------------
extern "C" void kernel_launch(void* const* d_in, const int* in_sizes, int n_in,
                              void* d_out, int out_size)
{
    const float* hidden  = (const float*)d_in[0];   // [2, 2048, 1024]
    const float* queries = (const float*)d_in[1];   // [4, 256, 1024]
    const float* comb    = (const float*)d_in[2];   // [4, 1024, 256]
    float* out = (float*)d_out;                     // [2, 2048, 1024]

    cudaFuncSetAttribute(k_gram, cudaFuncAttributeMaxDynamicSharedMemorySize, SMEM_GEMM);
    cudaFuncSetAttribute(k_b1,   cudaFuncAttributeMaxDynamicSharedMemorySize, SMEM_GEMM);
    cudaFuncSetAttribute(k_b2,   cudaFuncAttributeMaxDynamicSharedMemorySize, SMEM_GEMM);
    cudaFuncSetAttribute(k_c,    cudaFuncAttributeMaxDynamicSharedMemorySize, SMEM_GEMM);

    p_hid <<<dim3(16, 32, 2), 256>>>(hidden);
    p_comb<<<dim3(4, 16, 4), 256>>>(comb);
    p_q   <<<1024, 256>>>(queries);
    k_gram<<<dim3(4, 8, 8), 128, SMEM_GEMM>>>();
    k_gred<<<512, 256>>>();
    k_b1  <<<dim3(4, 32), 128, SMEM_GEMM>>>();
    k_tred<<<2048, 256>>>();
    k_b2  <<<dim3(4, 8, 4), 128, SMEM_GEMM>>>();
    k_mred<<<512, 256>>>();
    k_c   <<<dim3(32, 8), 128, SMEM_GEMM>>>(out);
}

// round 11
// speedup vs baseline: 1.0036x; 1.0036x over previous
#include <cuda_runtime.h>
#include <cuda_bf16.h>
#include <cstdint>

typedef unsigned int u32;
typedef unsigned short u16;

// ---------------------------------------------------------------------------
// Device-global scratch (no allocations allowed). All bf16 stored as ushort.
// ---------------------------------------------------------------------------
__device__ __align__(16) u16 g_XTh[8u*256*2048], g_XTl[8u*256*2048];  // X^T per (b,q): [f=256][t=2048]
__device__ __align__(16) u16 g_Xnh[2u*2048*1024], g_Xnl[2u*2048*1024];// hidden split: [b][t][e]
__device__ __align__(16) u16 g_CTh[16u*65536],   g_CTl[16u*65536];    // C^T per (a,q): [g=256][f=256]
__device__ __align__(16) u16 g_qh [4u*262144],   g_ql [4u*262144];    // queries split: [a][e=256][k=1024]
__device__ __align__(16) float g_Gp[8u*8*65536];                      // gram fp32 partials (z8)
__device__ __align__(16) u16 g_Gh[8u*65536], g_Gl[8u*65536];          // G per (b,q): [256][256] (symmetric)
__device__ __align__(16) u16 g_TTh[8u*262144], g_TTl[8u*262144];      // T^T split: [ba][g=256][k=1024]
__device__ __align__(16) float g_Mp[4u*8*65536];                      // fold fp32 partials (z4)
__device__ __align__(16) u16 g_Mth[8u*65536], g_Mtl[8u*65536];        // M^T per (b,a): [g=256][e=256]

// ---------------------------------------------------------------------------
__device__ __forceinline__ void mma_bf16(float* c, const u32* a, const u32* b) {
    asm("mma.sync.aligned.m16n8k16.row.col.f32.bf16.bf16.f32 "
        "{%0,%1,%2,%3}, {%4,%5,%6,%7}, {%8,%9}, {%0,%1,%2,%3};"
        : "+f"(c[0]), "+f"(c[1]), "+f"(c[2]), "+f"(c[3])
        : "r"(a[0]), "r"(a[1]), "r"(a[2]), "r"(a[3]), "r"(b[0]), "r"(b[1]));
}
__device__ __forceinline__ void ldsm_x4(u32* r, u32 saddr) {
    asm volatile("ldmatrix.sync.aligned.m8n8.x4.shared.b16 {%0,%1,%2,%3}, [%4];"
                 : "=r"(r[0]), "=r"(r[1]), "=r"(r[2]), "=r"(r[3]) : "r"(saddr));
}
__device__ __forceinline__ void cpa16(u32 dst, const void* src) {
    asm volatile("cp.async.cg.shared.global [%0], [%1], 16;" :: "r"(dst), "l"(src));
}
__device__ __forceinline__ void cpa_commit() {
    asm volatile("cp.async.commit_group;" ::: "memory");
}

__device__ __forceinline__ void split2(float v, u16& h, u16& l) {
    __nv_bfloat16 bh = __float2bfloat16(v);
    __nv_bfloat16 bl = __float2bfloat16(v - __bfloat162float(bh));
    h = *reinterpret_cast<u16*>(&bh);
    l = *reinterpret_cast<u16*>(&bl);
}

// SMEM tile: 128 rows x 32 bf16, row stride 40 u16 (80B).
constexpr int SK = 40;
constexpr int TSZ = 128 * SK;                   // u16 per tile
constexpr int BUF = 4 * TSZ;                    // u16 per buffer (Ah,Al,Bh,Bl)
constexpr int SMEM_GEMM = 2 * BUF * 2;          // bytes = 81920

// ---------------------------------------------------------------------------
// cp.async fill of one 4-tile chunk (A/B hi+lo, 128x32 each). 128 threads.
// ---------------------------------------------------------------------------
__device__ __forceinline__ void issue_chunk(u16* buf,
    const u16* __restrict__ Ah, const u16* __restrict__ Al, size_t lda,
    const u16* __restrict__ Bh, const u16* __restrict__ Bl, size_t ldb, int k0)
{
    u16* sAh = buf;           u16* sAl = buf + TSZ;
    u16* sBh = buf + 2 * TSZ; u16* sBl = buf + 3 * TSZ;
    #pragma unroll
    for (int u = threadIdx.x; u < 512; u += 128) {
        int row = u >> 2, c = u & 3;
        int so = row * SK + c * 8;
        size_t goA = (size_t)row * lda + k0 + c * 8;
        size_t goB = (size_t)row * ldb + k0 + c * 8;
        cpa16((u32)__cvta_generic_to_shared(sAh + so), Ah + goA);
        cpa16((u32)__cvta_generic_to_shared(sAl + so), Al + goA);
        cpa16((u32)__cvta_generic_to_shared(sBh + so), Bh + goB);
        cpa16((u32)__cvta_generic_to_shared(sBl + so), Bl + goB);
    }
    cpa_commit();
}

// ---------------------------------------------------------------------------
// Core: C[128,128](fp32) = sum_k (Ah+Al)[128,k]*(Bh+Bl)[128,k]^T (hh+hl+lh)
// 128 threads = 4 warps (2m x 2n), warp tile 64x64. Double-buffered cp.async,
// ldmatrix.x4 loads. MMA issued TERM-OUTER: all 32 hh, then 32 hl, then 32 lh
// so same-accumulator reuse distance is 32 MMAs (no dependent chains).
// SPLIT_OUT: write bf16 hi/lo (Ch/Cl) instead of fp32 C.
// ---------------------------------------------------------------------------
template <bool SPLIT_OUT>
__device__ void gemm_ss(const u16* __restrict__ Ah, const u16* __restrict__ Al, size_t lda,
                        const u16* __restrict__ Bh, const u16* __restrict__ Bl, size_t ldb,
                        int kbeg, int kend,
                        float* __restrict__ C, u16* __restrict__ Ch, u16* __restrict__ Cl,
                        size_t ldc)
{
    extern __shared__ __align__(16) u16 dsmem[];
    u16* bufs[2] = { dsmem, dsmem + BUF };

    const int tid = threadIdx.x, w = tid >> 5, lane = tid & 31;
    const int wm = (w >> 1) * 64, wn = (w & 1) * 64;
    const int ty = lane >> 2, tk = lane & 3;

    float acc[4][8][4] = {};   // [mt][nt][frag]  (64x64 warp tile)

    const int nchunk = (kend - kbeg) >> 5;
    issue_chunk(bufs[0], Ah, Al, lda, Bh, Bl, ldb, kbeg);

    for (int i = 0; i < nchunk; i++) {
        const bool has_next = (i + 1) < nchunk;
        if (has_next)
            issue_chunk(bufs[(i + 1) & 1], Ah, Al, lda, Bh, Bl, ldb, kbeg + (i + 1) * 32);
        if (has_next) asm volatile("cp.async.wait_group 1;" ::: "memory");
        else          asm volatile("cp.async.wait_group 0;" ::: "memory");
        __syncthreads();

        u16* buf = bufs[i & 1];
        const u32 bAh = (u32)__cvta_generic_to_shared(buf);
        const u32 bAl = bAh + TSZ * 2;
        const u32 bBh = bAh + 2 * TSZ * 2;
        const u32 bBl = bAh + 3 * TSZ * 2;

        #pragma unroll
        for (int ks = 0; ks < 2; ks++) {
            const int kb = ks * 16;
            // A fragments (hi+lo) for all 4 mt
            u32 ah[4][4], al[4][4];
            #pragma unroll
            for (int mt = 0; mt < 4; mt++) {
                u32 off = ((wm + mt * 16 + (lane & 15)) * SK + kb + (lane >> 4) * 8) * 2;
                ldsm_x4(ah[mt], bAh + off);
                ldsm_x4(al[mt], bAl + off);
            }
            // B fragments (hi+lo) for all 4 np (each = two n8 tiles)
            u32 bh4[4][4], bl4[4][4];
            #pragma unroll
            for (int np = 0; np < 4; np++) {
                u32 off = ((wn + np * 16 + (lane & 7) + ((lane >> 4) & 1) * 8) * SK
                           + kb + ((lane >> 3) & 1) * 8) * 2;
                ldsm_x4(bh4[np], bBh + off);
                ldsm_x4(bl4[np], bBl + off);
            }
            // term hh — 32 independent MMAs
            #pragma unroll
            for (int np = 0; np < 4; np++)
                #pragma unroll
                for (int mt = 0; mt < 4; mt++) {
                    mma_bf16(acc[mt][2*np],   ah[mt], bh4[np]);
                    mma_bf16(acc[mt][2*np+1], ah[mt], bh4[np] + 2);
                }
            // term hl
            #pragma unroll
            for (int np = 0; np < 4; np++)
                #pragma unroll
                for (int mt = 0; mt < 4; mt++) {
                    mma_bf16(acc[mt][2*np],   ah[mt], bl4[np]);
                    mma_bf16(acc[mt][2*np+1], ah[mt], bl4[np] + 2);
                }
            // term lh
            #pragma unroll
            for (int np = 0; np < 4; np++)
                #pragma unroll
                for (int mt = 0; mt < 4; mt++) {
                    mma_bf16(acc[mt][2*np],   al[mt], bh4[np]);
                    mma_bf16(acc[mt][2*np+1], al[mt], bh4[np] + 2);
                }
        }
        __syncthreads();
    }

    // epilogue
    #pragma unroll
    for (int mt = 0; mt < 4; mt++) {
        int m = wm + mt * 16 + ty;
        #pragma unroll
        for (int nt = 0; nt < 8; nt++) {
            int n = wn + nt * 8 + tk * 2;
            if (SPLIT_OUT) {
                u16 h0, l0, h1, l1, h2, l2, h3, l3;
                split2(acc[mt][nt][0], h0, l0); split2(acc[mt][nt][1], h1, l1);
                split2(acc[mt][nt][2], h2, l2); split2(acc[mt][nt][3], h3, l3);
                *reinterpret_cast<ushort2*>(&Ch[(size_t)m * ldc + n]) = make_ushort2(h0, h1);
                *reinterpret_cast<ushort2*>(&Cl[(size_t)m * ldc + n]) = make_ushort2(l0, l1);
                *reinterpret_cast<ushort2*>(&Ch[(size_t)(m + 8) * ldc + n]) = make_ushort2(h2, h3);
                *reinterpret_cast<ushort2*>(&Cl[(size_t)(m + 8) * ldc + n]) = make_ushort2(l2, l3);
            } else {
                *reinterpret_cast<float2*>(&C[(size_t)m * ldc + n]) =
                    make_float2(acc[mt][nt][0], acc[mt][nt][1]);
                *reinterpret_cast<float2*>(&C[(size_t)(m + 8) * ldc + n]) =
                    make_float2(acc[mt][nt][2], acc[mt][nt][3]);
            }
        }
    }
}

// ---------------------------------------------------------------------------
// Prep kernels (fp32 -> bf16 hi/lo, with transposes)
// ---------------------------------------------------------------------------
__global__ void __launch_bounds__(256) p_hid(const float* __restrict__ hidden)
{
    __shared__ float tile[64][65];
    const int tid = threadIdx.x;
    const int e0 = blockIdx.x * 64, t0 = blockIdx.y * 64, b = blockIdx.z;
    const size_t base = (size_t)b * 2048 * 1024;
    for (int i = tid; i < 4096; i += 256) {
        int r = i >> 6, c = i & 63;
        float v = hidden[base + (size_t)(t0 + r) * 1024 + e0 + c];
        tile[r][c] = v;
        u16 h, l; split2(v, h, l);
        size_t o = base + (size_t)(t0 + r) * 1024 + e0 + c;
        g_Xnh[o] = h; g_Xnl[o] = l;
    }
    __syncthreads();
    const int pair = b * 4 + (e0 >> 8), f0 = e0 & 255;
    for (int i = tid; i < 4096; i += 256) {
        int fl = i >> 6, tl = i & 63;
        u16 h, l; split2(tile[tl][fl], h, l);
        size_t o = (size_t)pair * 524288 + (size_t)(f0 + fl) * 2048 + t0 + tl;
        g_XTh[o] = h; g_XTl[o] = l;
    }
}

__global__ void __launch_bounds__(256) p_comb(const float* __restrict__ comb)
{
    __shared__ float tile[64][65];
    const int tid = threadIdx.x;
    const int g0 = blockIdx.x * 64, k0 = blockIdx.y * 64, a = blockIdx.z;
    for (int i = tid; i < 4096; i += 256) {
        int r = i >> 6, c = i & 63;
        tile[r][c] = comb[(size_t)a * 262144 + (size_t)(k0 + r) * 256 + g0 + c];
    }
    __syncthreads();
    const int q = k0 >> 8, f0 = k0 & 255;
    for (int i = tid; i < 4096; i += 256) {
        int gl = i >> 6, fl = i & 63;
        u16 h, l; split2(tile[fl][gl], h, l);
        size_t o = (size_t)(a * 4 + q) * 65536 + (size_t)(g0 + gl) * 256 + f0 + fl;
        g_CTh[o] = h; g_CTl[o] = l;
    }
}

__global__ void __launch_bounds__(256) p_q(const float* __restrict__ queries)
{
    const int i = blockIdx.x * 256 + threadIdx.x;      // 262144 float4
    float4 v = reinterpret_cast<const float4*>(queries)[i];
    ushort4 h, l;
    split2(v.x, h.x, l.x); split2(v.y, h.y, l.y);
    split2(v.z, h.z, l.z); split2(v.w, h.w, l.w);
    reinterpret_cast<ushort4*>(g_qh)[i] = h;
    reinterpret_cast<ushort4*>(g_ql)[i] = l;
}

// ---------------------------------------------------------------------------
// GEMM stages (128 threads each)
// ---------------------------------------------------------------------------
// Gram: D[f,f'] = sum_t XT[f,t] XT[f',t]  — grid (4, 8 pairs, 8 z)
__global__ void __launch_bounds__(128) k_gram()
{
    const int pair = blockIdx.y, z = blockIdx.z;
    const int m0 = (blockIdx.x >> 1) * 128, n0 = (blockIdx.x & 1) * 128;
    const u16* base_h = g_XTh + (size_t)pair * 524288;
    const u16* base_l = g_XTl + (size_t)pair * 524288;
    float* C = g_Gp + (size_t)(z * 8 + pair) * 65536 + (size_t)m0 * 256 + n0;
    gemm_ss<false>(base_h + (size_t)m0 * 2048, base_l + (size_t)m0 * 2048, 2048,
                   base_h + (size_t)n0 * 2048, base_l + (size_t)n0 * 2048, 2048,
                   z * 256, z * 256 + 256, C, nullptr, nullptr, 256);
}

__global__ void __launch_bounds__(256) k_gred()
{
    const int i = blockIdx.x * 256 + threadIdx.x;      // 131072 float4
    const float4* P = reinterpret_cast<const float4*>(g_Gp);
    float4 s = P[i];
    #pragma unroll
    for (int z = 1; z < 8; z++) {
        float4 t = P[i + (size_t)z * 131072];
        s.x += t.x; s.y += t.y; s.z += t.z; s.w += t.w;
    }
    ushort4 h, l;
    split2(s.x, h.x, l.x); split2(s.y, h.y, l.y);
    split2(s.z, h.z, l.z); split2(s.w, h.w, l.w);
    reinterpret_cast<ushort4*>(g_Gh)[i] = h;
    reinterpret_cast<ushort4*>(g_Gl)[i] = l;
}

// B1: TT[ba][g, q*256+f] = sum_{f'} CT[a,q][g,f'] G[b,q][f,f'] — grid (4, 32)
// split-fused epilogue (no k_tred)
__global__ void __launch_bounds__(128) k_b1()
{
    const int combo = blockIdx.y, q = combo & 3, ba = combo >> 2;
    const int a = ba & 3, b = ba >> 2;
    const int m0 = (blockIdx.x >> 1) * 128, n0 = (blockIdx.x & 1) * 128;
    const u16* Ah = g_CTh + (size_t)(a * 4 + q) * 65536 + (size_t)m0 * 256;
    const u16* Al = g_CTl + (size_t)(a * 4 + q) * 65536 + (size_t)m0 * 256;
    const u16* Bh = g_Gh + (size_t)(b * 4 + q) * 65536 + (size_t)n0 * 256;
    const u16* Bl = g_Gl + (size_t)(b * 4 + q) * 65536 + (size_t)n0 * 256;
    size_t off = (size_t)ba * 262144 + (size_t)m0 * 1024 + q * 256 + n0;
    gemm_ss<true>(Ah, Al, 256, Bh, Bl, 256, 0, 256,
                  nullptr, g_TTh + off, g_TTl + off, 1024);
}

// B2: Mt[g,e] = sum_k TT[ba][g,k] q[a][e,k] — grid (4, 8 ba, 4 z)
__global__ void __launch_bounds__(128) k_b2()
{
    const int ba = blockIdx.y, z = blockIdx.z, a = ba & 3;
    const int m0 = (blockIdx.x >> 1) * 128, n0 = (blockIdx.x & 1) * 128;
    const u16* Ah = g_TTh + (size_t)ba * 262144 + (size_t)m0 * 1024;
    const u16* Al = g_TTl + (size_t)ba * 262144 + (size_t)m0 * 1024;
    const u16* Bh = g_qh + (size_t)a * 262144 + (size_t)n0 * 1024;
    const u16* Bl = g_ql + (size_t)a * 262144 + (size_t)n0 * 1024;
    float* C = g_Mp + (size_t)(z * 8 + ba) * 65536 + (size_t)m0 * 256 + n0;
    gemm_ss<false>(Ah, Al, 1024, Bh, Bl, 1024, z * 256, z * 256 + 256,
                   C, nullptr, nullptr, 256);
}

__global__ void __launch_bounds__(256) k_mred()
{
    const int i = blockIdx.x * 256 + threadIdx.x;      // 131072 float4
    const float4* P = reinterpret_cast<const float4*>(g_Mp);
    float4 s = P[i];
    #pragma unroll
    for (int z = 1; z < 4; z++) {
        float4 t = P[i + (size_t)z * 131072];
        s.x += t.x; s.y += t.y; s.z += t.z; s.w += t.w;
    }
    ushort4 h, l;
    split2(s.x, h.x, l.x); split2(s.y, h.y, l.y);
    split2(s.z, h.z, l.z); split2(s.w, h.w, l.w);
    reinterpret_cast<ushort4*>(g_Mth)[i] = h;
    reinterpret_cast<ushort4*>(g_Mtl)[i] = l;
}

// C: out[b,t,a*256+g] = sum_e Xn[b,t,a*256+e] Mt[ba][g,e] — grid (32, 8 ba)
__global__ void __launch_bounds__(128) k_c(float* __restrict__ out)
{
    const int ba = blockIdx.y, b = ba >> 2, a = ba & 3;
    const int m0 = (blockIdx.x >> 1) * 128, n0 = (blockIdx.x & 1) * 128;
    const u16* Ah = g_Xnh + (size_t)b * 2097152 + (size_t)m0 * 1024 + a * 256;
    const u16* Al = g_Xnl + (size_t)b * 2097152 + (size_t)m0 * 1024 + a * 256;
    const u16* Bh = g_Mth + (size_t)ba * 65536 + (size_t)n0 * 256;
    const u16* Bl = g_Mtl + (size_t)ba * 65536 + (size_t)n0 * 256;
    float* C = out + (size_t)b * 2097152 + (size_t)m0 * 1024 + a * 256 + n0;
    gemm_ss<false>(Ah, Al, 1024, Bh, Bl, 256, 0, 256, C, nullptr, nullptr, 1024);
}

// ---------------------------------------------------------------------------
extern "C" void kernel_launch(void* const* d_in, const int* in_sizes, int n_in,
                              void* d_out, int out_size)
{
    const float* hidden  = (const float*)d_in[0];   // [2, 2048, 1024]
    const float* queries = (const float*)d_in[1];   // [4, 256, 1024]
    const float* comb    = (const float*)d_in[2];   // [4, 1024, 256]
    float* out = (float*)d_out;                     // [2, 2048, 1024]

    cudaFuncSetAttribute(k_gram, cudaFuncAttributeMaxDynamicSharedMemorySize, SMEM_GEMM);
    cudaFuncSetAttribute(k_b1,   cudaFuncAttributeMaxDynamicSharedMemorySize, SMEM_GEMM);
    cudaFuncSetAttribute(k_b2,   cudaFuncAttributeMaxDynamicSharedMemorySize, SMEM_GEMM);
    cudaFuncSetAttribute(k_c,    cudaFuncAttributeMaxDynamicSharedMemorySize, SMEM_GEMM);

    p_hid <<<dim3(16, 32, 2), 256>>>(hidden);
    p_comb<<<dim3(4, 16, 4), 256>>>(comb);
    p_q   <<<1024, 256>>>(queries);
    k_gram<<<dim3(4, 8, 8), 128, SMEM_GEMM>>>();
    k_gred<<<512, 256>>>();
    k_b1  <<<dim3(4, 32), 128, SMEM_GEMM>>>();
    k_b2  <<<dim3(4, 8, 4), 128, SMEM_GEMM>>>();
    k_mred<<<512, 256>>>();
    k_c   <<<dim3(32, 8), 128, SMEM_GEMM>>>(out);
}